// round 6
// baseline (speedup 1.0000x reference)
#include <cuda_runtime.h>
#include <cuda_bf16.h>

typedef unsigned long long ull;

// Problem constants
#define BB    8
#define NN    4096
#define WROW  128          // 4096/32 bitmask words per row
#define ROWS  (BB*NN)      // 32768
#define INDIM 16420
#define HID   128
#define NACT  16
#define CK    514          // fc1 split-K chunk (32*514 >= 16420)
#define NQ    8            // column strips per row in agg (512 cols each)

// ---------------- scratch (static __device__, no allocations) ----------------
__device__ unsigned g_bits[(size_t)ROWS * WROW];   // 16 MB packed adjacency (with self loops)
__device__ float    g_dinv[ROWS];
__device__ float4   g_v [ROWS];                    // dinv * (x @ W1)
__device__ float4   g_v2[ROWS];                    // dinv * (h @ W2)
__device__ float4   g_h2[ROWS];                    // final GCN output h (layer2)
__device__ float4   g_pa[NQ * ROWS];               // layer1 partial sums (col strips)
__device__ float4   g_pb[NQ * ROWS];               // layer2 partial sums
__device__ float    g_zacc[BB * HID];

// ---------------- K1: adj -> bitmask + dinv + v1 + zacc init ----------------
// 2 rows per block; all 8 int4 loads hoisted up front for MLP=8.
__global__ void __launch_bounds__(256) prep_kernel(
    const int* __restrict__ adj, const float* __restrict__ x,
    const float* __restrict__ W1, const float* __restrict__ fcb1)
{
    int bx   = blockIdx.x;                // 0..16383
    int row0 = bx * 2;
    int row1 = row0 + 1;
    int t    = threadIdx.x;
    int lane = t & 31;

    // fused zacc init (first 4 blocks cover rows 0..7)
    if (bx < 4 && t < HID) {
        g_zacc[row0 * HID + t] = fcb1[t];
        g_zacc[row1 * HID + t] = fcb1[t];
    }

    const int4* a0 = (const int4*)(adj + ((size_t)row0 << 12));
    const int4* a1 = (const int4*)(adj + ((size_t)row1 << 12));
    unsigned* b0 = g_bits + ((size_t)row0 << 7);
    unsigned* b1 = g_bits + ((size_t)row1 << 7);

    int4 L0[4], L1[4];
#pragma unroll
    for (int it = 0; it < 4; ++it) { L0[it] = a0[it * 256 + t]; }
#pragma unroll
    for (int it = 0; it < 4; ++it) { L1[it] = a1[it * 256 + t]; }

    int i0 = row0 & (NN - 1);
    int i1 = row1 & (NN - 1);

    unsigned cnt = 0;   // low 16: row0 degree, high 16: row1 degree
#pragma unroll
    for (int it = 0; it < 4; ++it) {
        int j0 = it * 1024 + t * 4;
        {
            int4 v = L0[it];
            unsigned nib = (unsigned)((v.x != 0) | ((v.y != 0) << 1) |
                                      ((v.z != 0) << 2) | ((v.w != 0) << 3));
            unsigned dio = (unsigned)(i0 - j0);
            if (dio < 4u) nib |= 1u << dio;
            unsigned w = nib << ((lane & 7) * 4);
            w |= __shfl_xor_sync(0xffffffffu, w, 1);
            w |= __shfl_xor_sync(0xffffffffu, w, 2);
            w |= __shfl_xor_sync(0xffffffffu, w, 4);
            if ((lane & 7) == 0) {
                b0[j0 >> 5] = w;
                cnt += __popc(w);
            }
        }
        {
            int4 v = L1[it];
            unsigned nib = (unsigned)((v.x != 0) | ((v.y != 0) << 1) |
                                      ((v.z != 0) << 2) | ((v.w != 0) << 3));
            unsigned dio = (unsigned)(i1 - j0);
            if (dio < 4u) nib |= 1u << dio;
            unsigned w = nib << ((lane & 7) * 4);
            w |= __shfl_xor_sync(0xffffffffu, w, 1);
            w |= __shfl_xor_sync(0xffffffffu, w, 2);
            w |= __shfl_xor_sync(0xffffffffu, w, 4);
            if ((lane & 7) == 0) {
                b1[j0 >> 5] = w;
                cnt += __popc(w) << 16;
            }
        }
    }
    // block reduce (packed 16+16)
    cnt += __shfl_down_sync(0xffffffffu, cnt, 16);
    cnt += __shfl_down_sync(0xffffffffu, cnt, 8);
    cnt += __shfl_down_sync(0xffffffffu, cnt, 4);
    cnt += __shfl_down_sync(0xffffffffu, cnt, 2);
    cnt += __shfl_down_sync(0xffffffffu, cnt, 1);
    __shared__ unsigned scnt[8];
    if (lane == 0) scnt[t >> 5] = cnt;
    __syncthreads();
    if (t < 2) {
        unsigned tot = 0;
#pragma unroll
        for (int w = 0; w < 8; ++w) tot += scnt[w];
        unsigned deg = (t == 0) ? (tot & 0xFFFFu) : (tot >> 16);
        int row = row0 + t;
        float d = rsqrtf((float)deg);
        g_dinv[row] = d;
        float x0 = x[row*3], x1 = x[row*3+1], x2 = x[row*3+2];
        float u0 = x0*W1[0] + x1*W1[3] + x2*W1[6];
        float u1 = x0*W1[1] + x1*W1[4] + x2*W1[7];
        float u2 = x0*W1[2] + x1*W1[5] + x2*W1[8];
        g_v[row] = make_float4(d*u0, d*u1, d*u2, 0.f);
    }
}

// ---------------- masked aggregation: broadcast LDS + 2 rows/lane ----------------
// v staged as (x,y,z,z); per column: one broadcast ld.shared.v2.b64 pair shared
// by 64 rows (warp), per row: fused bit-test + two packed add.rn.f32x2.

#define COLACC2(AXY, AZZ, WB, BIT, VXY, VZZ)                       \
    asm volatile("{\n\t"                                           \
        ".reg .pred p;\n\t"                                        \
        ".reg .b32 r;\n\t"                                         \
        "and.b32 r, %2, %3;\n\t"                                   \
        "setp.ne.b32 p, r, 0;\n\t"                                 \
        "@p add.rn.f32x2 %0, %0, %4;\n\t"                          \
        "@p add.rn.f32x2 %1, %1, %5;\n\t"                          \
        "}"                                                        \
        : "+l"(AXY), "+l"(AZZ)                                     \
        : "r"(WB), "r"(BIT), "l"(VXY), "l"(VZZ))

__device__ __forceinline__ void wordacc(
    unsigned w0, unsigned w1, unsigned base,
    ull& a0xy, ull& a0zz, ull& a1xy, ull& a1zz)
{
#pragma unroll
    for (int c = 0; c < 32; ++c) {
        ull vxy, vzz;
        asm volatile("ld.shared.v2.b64 {%0,%1}, [%2];"
                     : "=l"(vxy), "=l"(vzz) : "r"(base + c * 16));
        COLACC2(a0xy, a0zz, w0, 1u << c, vxy, vzz);
        COLACC2(a1xy, a1zz, w1, 1u << c, vxy, vzz);
    }
}

// grid = 512 blocks: (b in 8) x (rowtile in 8: 512 rows) x (strip in 8: 512 cols)
// block = 256 threads (8 warps); lane owns rows {base+lane, base+lane+32}
template<int L>
__global__ void __launch_bounds__(256) agg_kernel()
{
    __shared__ float4 sv[512];

    const float4* vin  = (L == 0) ? g_v  : g_v2;
    float4*       part = (L == 0) ? g_pa : g_pb;

    int bx   = blockIdx.x;
    int b    = bx >> 6;
    int rt   = (bx >> 3) & 7;
    int q    = bx & 7;
    int t    = threadIdx.x;
    int warp = t >> 5, lane = t & 31;

    // stage v strip as (x,y,z,z)
    const float4* gv = vin + b * NN + q * 512;
#pragma unroll
    for (int s = t; s < 512; s += 256) {
        float4 v = gv[s];
        sv[s] = make_float4(v.x, v.y, v.z, v.z);
    }
    __syncthreads();

    int r0 = b * NN + rt * 512 + warp * 64 + lane;
    int r1 = r0 + 32;
    const uint4* gw0 = (const uint4*)(g_bits + (size_t)r0 * WROW + q * 16);
    const uint4* gw1 = (const uint4*)(g_bits + (size_t)r1 * WROW + q * 16);

    unsigned sva = (unsigned)__cvta_generic_to_shared(sv);

    ull a0xy = 0ull, a0zz = 0ull, a1xy = 0ull, a1zz = 0ull;

#pragma unroll 1
    for (int wg = 0; wg < 4; ++wg) {
        uint4 wa = gw0[wg];
        uint4 wb = gw1[wg];
        unsigned base = sva + (unsigned)wg * 2048;   // 4 words * 512B
        wordacc(wa.x, wb.x, base,        a0xy, a0zz, a1xy, a1zz);
        wordacc(wa.y, wb.y, base + 512,  a0xy, a0zz, a1xy, a1zz);
        wordacc(wa.z, wb.z, base + 1024, a0xy, a0zz, a1xy, a1zz);
        wordacc(wa.w, wb.w, base + 1536, a0xy, a0zz, a1xy, a1zz);
    }

    float x0, y0, z0, d0, x1, y1, z1, d1;
    asm volatile("mov.b64 {%0, %1}, %2;" : "=f"(x0), "=f"(y0) : "l"(a0xy));
    asm volatile("mov.b64 {%0, %1}, %2;" : "=f"(z0), "=f"(d0) : "l"(a0zz));
    asm volatile("mov.b64 {%0, %1}, %2;" : "=f"(x1), "=f"(y1) : "l"(a1xy));
    asm volatile("mov.b64 {%0, %1}, %2;" : "=f"(z1), "=f"(d1) : "l"(a1zz));

    part[q * ROWS + r0] = make_float4(x0, y0, z0, 0.f);
    part[q * ROWS + r1] = make_float4(x1, y1, z1, 0.f);
}

// ---------------- combine layer1 partials, relu, v2 = dinv * (h @ W2) ----------------
__global__ void v2_kernel(const float* __restrict__ W2, const float* __restrict__ b1)
{
    int id = blockIdx.x * blockDim.x + threadIdx.x;
    if (id >= ROWS) return;
    float sx = 0.f, sy = 0.f, sz = 0.f;
#pragma unroll
    for (int qq = 0; qq < NQ; ++qq) {
        float4 p = g_pa[qq * ROWS + id];
        sx += p.x; sy += p.y; sz += p.z;
    }
    float d = g_dinv[id];
    float h0 = fmaxf(d * sx + b1[0], 0.f);
    float h1 = fmaxf(d * sy + b1[1], 0.f);
    float h2 = fmaxf(d * sz + b1[2], 0.f);
    float u0 = h0*W2[0] + h1*W2[3] + h2*W2[6];
    float u1 = h0*W2[1] + h1*W2[4] + h2*W2[7];
    float u2 = h0*W2[2] + h1*W2[5] + h2*W2[8];
    g_v2[id] = make_float4(d*u0, d*u1, d*u2, 0.f);
}

// ---------------- combine layer2 partials -> final GCN h ----------------
__global__ void combine2_kernel(const float* __restrict__ b2)
{
    int id = blockIdx.x * blockDim.x + threadIdx.x;
    if (id >= ROWS) return;
    float sx = 0.f, sy = 0.f, sz = 0.f;
#pragma unroll
    for (int qq = 0; qq < NQ; ++qq) {
        float4 p = g_pb[qq * ROWS + id];
        sx += p.x; sy += p.y; sz += p.z;
    }
    float d = g_dinv[id];
    g_h2[id] = make_float4(d * sx + b2[0], d * sy + b2[1], d * sz + b2[2], 0.f);
}

// ---------------- fc1 split-K, z built on the fly, atomic accumulate ----------------
__global__ void __launch_bounds__(128) fc1_kernel(
    const float* __restrict__ idxin, const float* __restrict__ y,
    const float* __restrict__ fcW1)
{
    __shared__ float zc[CK];
    int bx = blockIdx.x;
    int b  = bx >> 5;
    int s  = bx & 31;
    int k0 = s * CK;
    int klen = min(CK, INDIM - k0);
    int t = threadIdx.x;

    for (int kk = t; kk < klen; kk += 128) {
        int k = k0 + kk;
        float z;
        if (k < NN) {
            z = idxin[b * NN + k];
        } else if (k < NN + 3 * NN) {
            int g = k - NN;
            int i = g / 3;
            int f = g - i * 3;
            z = ((const float*)&g_h2[b * NN + i])[f];
        } else {
            z = y[b * 36 + (k - (NN + 3 * NN))];
        }
        zc[kk] = z;
    }
    __syncthreads();

    float acc = 0.f;
    const float* wcol = fcW1 + (size_t)k0 * HID + t;
    int kk = 0;
    for (; kk + 4 <= klen; kk += 4) {
        acc += zc[kk+0] * wcol[(size_t)(kk+0) * HID];
        acc += zc[kk+1] * wcol[(size_t)(kk+1) * HID];
        acc += zc[kk+2] * wcol[(size_t)(kk+2) * HID];
        acc += zc[kk+3] * wcol[(size_t)(kk+3) * HID];
    }
    for (; kk < klen; ++kk)
        acc += zc[kk] * wcol[(size_t)kk * HID];

    atomicAdd(&g_zacc[b * HID + t], acc);
}

// ---------------- relu + fc2 ----------------
__global__ void __launch_bounds__(128) fin_kernel(
    const float* __restrict__ fcW2, const float* __restrict__ fcb2, float* __restrict__ out)
{
    __shared__ float sm[HID];
    int b = blockIdx.x, t = threadIdx.x;
    sm[t] = fmaxf(g_zacc[b * HID + t], 0.f);
    __syncthreads();
    if (t < NACT) {
        float o = fcb2[t];
#pragma unroll 8
        for (int h = 0; h < HID; ++h)
            o += sm[h] * fcW2[h * NACT + t];
        out[b * NACT + t] = o;
    }
}

// ---------------- launch ----------------
extern "C" void kernel_launch(void* const* d_in, const int* in_sizes, int n_in,
                              void* d_out, int out_size)
{
    const float* idxin = (const float*)d_in[0];   // [8,4096]
    const float* x     = (const float*)d_in[1];   // [8,4096,3]
    const float* y     = (const float*)d_in[2];   // [8,12,3]
    const int*   adj   = (const int*)  d_in[3];   // [8,4096,4096]
    const float* W1    = (const float*)d_in[4];
    const float* b1    = (const float*)d_in[5];
    const float* W2    = (const float*)d_in[6];
    const float* b2    = (const float*)d_in[7];
    const float* fcW1  = (const float*)d_in[8];
    const float* fcb1  = (const float*)d_in[9];
    const float* fcW2  = (const float*)d_in[10];
    const float* fcb2  = (const float*)d_in[11];
    float* out = (float*)d_out;

    prep_kernel<<<ROWS / 2, 256>>>(adj, x, W1, fcb1);
    agg_kernel<0><<<512, 256>>>();
    v2_kernel<<<ROWS / 256, 256>>>(W2, b1);
    agg_kernel<1><<<512, 256>>>();
    combine2_kernel<<<ROWS / 256, 256>>>(b2);
    fc1_kernel<<<BB * 32, 128>>>(idxin, y, fcW1);
    fin_kernel<<<BB, 128>>>(fcW2, fcb2, out);
}

// round 7
// speedup vs baseline: 1.2501x; 1.2501x over previous
#include <cuda_runtime.h>
#include <cuda_bf16.h>

typedef unsigned long long ull;

// Problem constants
#define BB    8
#define NN    4096
#define WROW  128          // 4096/32 bitmask words per row
#define ROWS  (BB*NN)      // 32768
#define INDIM 16420
#define HID   128
#define NACT  16
#define CK    514          // fc1 split-K chunk (32*514 >= 16420)
#define NQ    8            // column strips per row in agg (512 cols each)

// ---------------- scratch (static __device__, no allocations) ----------------
__device__ unsigned g_bits[(size_t)ROWS * WROW];   // 16 MB packed adjacency (with self loops)
__device__ float    g_dinv[ROWS];
__device__ float4   g_v [ROWS];                    // dinv * (x @ W1)
__device__ float4   g_v2[ROWS];                    // dinv * (h @ W2)
__device__ float4   g_h2[ROWS];                    // final GCN output h (layer2)
__device__ float4   g_pa[NQ * ROWS];               // layer1 partial sums (col strips)
__device__ float4   g_pb[NQ * ROWS];               // layer2 partial sums
__device__ float    g_zacc[BB * HID];

// ---------------- K1: adj -> bitmask + dinv + v1 + zacc init ----------------
__global__ void __launch_bounds__(256) prep_kernel(
    const int* __restrict__ adj, const float* __restrict__ x,
    const float* __restrict__ W1, const float* __restrict__ fcb1)
{
    int bx   = blockIdx.x;                // 0..16383
    int row0 = bx * 2;
    int row1 = row0 + 1;
    int t    = threadIdx.x;
    int lane = t & 31;

    if (bx < 4 && t < HID) {
        g_zacc[row0 * HID + t] = fcb1[t];
        g_zacc[row1 * HID + t] = fcb1[t];
    }

    const int4* a0 = (const int4*)(adj + ((size_t)row0 << 12));
    const int4* a1 = (const int4*)(adj + ((size_t)row1 << 12));
    unsigned* b0 = g_bits + ((size_t)row0 << 7);
    unsigned* b1 = g_bits + ((size_t)row1 << 7);

    int4 L0[4], L1[4];
#pragma unroll
    for (int it = 0; it < 4; ++it) { L0[it] = a0[it * 256 + t]; }
#pragma unroll
    for (int it = 0; it < 4; ++it) { L1[it] = a1[it * 256 + t]; }

    int i0 = row0 & (NN - 1);
    int i1 = row1 & (NN - 1);

    unsigned cnt = 0;   // low 16: row0 degree, high 16: row1 degree
#pragma unroll
    for (int it = 0; it < 4; ++it) {
        int j0 = it * 1024 + t * 4;
        {
            int4 v = L0[it];
            unsigned nib = (unsigned)((v.x != 0) | ((v.y != 0) << 1) |
                                      ((v.z != 0) << 2) | ((v.w != 0) << 3));
            unsigned dio = (unsigned)(i0 - j0);
            if (dio < 4u) nib |= 1u << dio;
            unsigned w = nib << ((lane & 7) * 4);
            w |= __shfl_xor_sync(0xffffffffu, w, 1);
            w |= __shfl_xor_sync(0xffffffffu, w, 2);
            w |= __shfl_xor_sync(0xffffffffu, w, 4);
            if ((lane & 7) == 0) {
                b0[j0 >> 5] = w;
                cnt += __popc(w);
            }
        }
        {
            int4 v = L1[it];
            unsigned nib = (unsigned)((v.x != 0) | ((v.y != 0) << 1) |
                                      ((v.z != 0) << 2) | ((v.w != 0) << 3));
            unsigned dio = (unsigned)(i1 - j0);
            if (dio < 4u) nib |= 1u << dio;
            unsigned w = nib << ((lane & 7) * 4);
            w |= __shfl_xor_sync(0xffffffffu, w, 1);
            w |= __shfl_xor_sync(0xffffffffu, w, 2);
            w |= __shfl_xor_sync(0xffffffffu, w, 4);
            if ((lane & 7) == 0) {
                b1[j0 >> 5] = w;
                cnt += __popc(w) << 16;
            }
        }
    }
    cnt += __shfl_down_sync(0xffffffffu, cnt, 16);
    cnt += __shfl_down_sync(0xffffffffu, cnt, 8);
    cnt += __shfl_down_sync(0xffffffffu, cnt, 4);
    cnt += __shfl_down_sync(0xffffffffu, cnt, 2);
    cnt += __shfl_down_sync(0xffffffffu, cnt, 1);
    __shared__ unsigned scnt[8];
    if (lane == 0) scnt[t >> 5] = cnt;
    __syncthreads();
    if (t < 2) {
        unsigned tot = 0;
#pragma unroll
        for (int w = 0; w < 8; ++w) tot += scnt[w];
        unsigned deg = (t == 0) ? (tot & 0xFFFFu) : (tot >> 16);
        int row = row0 + t;
        float d = rsqrtf((float)deg);
        g_dinv[row] = d;
        float x0 = x[row*3], x1 = x[row*3+1], x2 = x[row*3+2];
        float u0 = x0*W1[0] + x1*W1[3] + x2*W1[6];
        float u1 = x0*W1[1] + x1*W1[4] + x2*W1[7];
        float u2 = x0*W1[2] + x1*W1[5] + x2*W1[8];
        g_v[row] = make_float4(d*u0, d*u1, d*u2, 0.f);
    }
}

// ---------------- quad-LUT aggregation, conflict-free narrow gathers ----------
// Per 4 columns: 4-bit index selects one of 16 precomputed partial sums.
// (x,y) LUT entry = float2 in a 128B window (conflict-free LDS.64);
// z LUT entry = float in a 64B window (conflict-free LDS.32).
// Per (row, quad): SHF+LOP3 + 2 IMAD + LDS.64 + LDS.32 + add.rn.f32x2 + FADD.

// grid = 1024 blocks: (b in 8) x (rowtile in 16: 256 rows) x (strip in 8: 512 cols)
// 256 threads; thread = one (row, strip).
template<int L>
__global__ void __launch_bounds__(256) agg_kernel()
{
    __shared__ float2 sxy[128 * 16];   // 16 KB: quad-major, entry stride 8B
    __shared__ float  szl[128 * 16];   // 8 KB:  quad-major, entry stride 4B

    const float4* vin  = (L == 0) ? g_v  : g_v2;
    float4*       part = (L == 0) ? g_pa : g_pb;

    int bx = blockIdx.x;
    int b  = bx >> 7;
    int rt = (bx >> 3) & 15;
    int q  = bx & 7;
    int t  = threadIdx.x;

    // ---- build LUTs: thread t -> quad t>>1, entries (t&1)*8 .. +8 ----
    {
        int quad = t >> 1;
        const float4* vg = vin + b * NN + q * 512 + quad * 4;
        float4 v0 = vg[0], v1 = vg[1], v2 = vg[2], v3 = vg[3];
        int e0 = (t & 1) * 8;
        float2* exy = &sxy[quad * 16];
        float*  ez  = &szl[quad * 16];
#pragma unroll
        for (int e = 0; e < 8; ++e) {
            int i = e0 + e;
            float sx = 0.f, sy = 0.f, sz = 0.f;
            if (i & 1) { sx += v0.x; sy += v0.y; sz += v0.z; }
            if (i & 2) { sx += v1.x; sy += v1.y; sz += v1.z; }
            if (i & 4) { sx += v2.x; sy += v2.y; sz += v2.z; }
            if (i & 8) { sx += v3.x; sy += v3.y; sz += v3.z; }
            exy[i] = make_float2(sx, sy);
            ez[i]  = sz;
        }
    }
    __syncthreads();

    int row = b * NN + rt * 256 + t;

    // this row's 16 bitmask words for strip q
    const uint4* gw = (const uint4*)(g_bits + (size_t)row * WROW + q * 16);
    uint4 w0 = gw[0], w1 = gw[1], w2 = gw[2], w3 = gw[3];
    unsigned words[16] = { w0.x, w0.y, w0.z, w0.w, w1.x, w1.y, w1.z, w1.w,
                           w2.x, w2.y, w2.z, w2.w, w3.x, w3.y, w3.z, w3.w };

    unsigned bxy = (unsigned)__cvta_generic_to_shared(sxy);
    unsigned bz  = (unsigned)__cvta_generic_to_shared(szl);

    ull  accxy = 0ull;
    float accz = 0.f;

#pragma unroll
    for (int wl = 0; wl < 16; ++wl) {
        unsigned w = words[wl];
        unsigned rxy = bxy + wl * 1024;   // 8 quads * 128B
        unsigned rz  = bz  + wl * 512;    // 8 quads * 64B
#pragma unroll
        for (int k = 0; k < 8; ++k) {
            unsigned idx = (w >> (4 * k)) & 15u;
            unsigned axy = rxy + k * 128 + idx * 8;
            unsigned az  = rz  + k * 64  + idx * 4;
            ull vxy;
            asm volatile("ld.shared.b64 %0, [%1];" : "=l"(vxy) : "r"(axy));
            asm volatile("add.rn.f32x2 %0, %0, %1;" : "+l"(accxy) : "l"(vxy));
            float vz;
            asm volatile("ld.shared.f32 %0, [%1];" : "=f"(vz) : "r"(az));
            accz += vz;
        }
    }

    float ax, ay;
    asm volatile("mov.b64 {%0, %1}, %2;" : "=f"(ax), "=f"(ay) : "l"(accxy));
    part[q * ROWS + row] = make_float4(ax, ay, accz, 0.f);
}

// ---------------- combine layer1 partials, relu, v2 = dinv * (h @ W2) ----------------
__global__ void v2_kernel(const float* __restrict__ W2, const float* __restrict__ b1)
{
    int id = blockIdx.x * blockDim.x + threadIdx.x;
    if (id >= ROWS) return;
    float sx = 0.f, sy = 0.f, sz = 0.f;
#pragma unroll
    for (int qq = 0; qq < NQ; ++qq) {
        float4 p = g_pa[qq * ROWS + id];
        sx += p.x; sy += p.y; sz += p.z;
    }
    float d = g_dinv[id];
    float h0 = fmaxf(d * sx + b1[0], 0.f);
    float h1 = fmaxf(d * sy + b1[1], 0.f);
    float h2 = fmaxf(d * sz + b1[2], 0.f);
    float u0 = h0*W2[0] + h1*W2[3] + h2*W2[6];
    float u1 = h0*W2[1] + h1*W2[4] + h2*W2[7];
    float u2 = h0*W2[2] + h1*W2[5] + h2*W2[8];
    g_v2[id] = make_float4(d*u0, d*u1, d*u2, 0.f);
}

// ---------------- combine layer2 partials -> final GCN h ----------------
__global__ void combine2_kernel(const float* __restrict__ b2)
{
    int id = blockIdx.x * blockDim.x + threadIdx.x;
    if (id >= ROWS) return;
    float sx = 0.f, sy = 0.f, sz = 0.f;
#pragma unroll
    for (int qq = 0; qq < NQ; ++qq) {
        float4 p = g_pb[qq * ROWS + id];
        sx += p.x; sy += p.y; sz += p.z;
    }
    float d = g_dinv[id];
    g_h2[id] = make_float4(d * sx + b2[0], d * sy + b2[1], d * sz + b2[2], 0.f);
}

// ---------------- fc1 split-K, z built on the fly, atomic accumulate ----------------
__global__ void __launch_bounds__(128) fc1_kernel(
    const float* __restrict__ idxin, const float* __restrict__ y,
    const float* __restrict__ fcW1)
{
    __shared__ float zc[CK];
    int bx = blockIdx.x;
    int b  = bx >> 5;
    int s  = bx & 31;
    int k0 = s * CK;
    int klen = min(CK, INDIM - k0);
    int t = threadIdx.x;

    for (int kk = t; kk < klen; kk += 128) {
        int k = k0 + kk;
        float z;
        if (k < NN) {
            z = idxin[b * NN + k];
        } else if (k < NN + 3 * NN) {
            int g = k - NN;
            int i = g / 3;
            int f = g - i * 3;
            z = ((const float*)&g_h2[b * NN + i])[f];
        } else {
            z = y[b * 36 + (k - (NN + 3 * NN))];
        }
        zc[kk] = z;
    }
    __syncthreads();

    float acc = 0.f;
    const float* wcol = fcW1 + (size_t)k0 * HID + t;
    int kk = 0;
    for (; kk + 4 <= klen; kk += 4) {
        acc += zc[kk+0] * wcol[(size_t)(kk+0) * HID];
        acc += zc[kk+1] * wcol[(size_t)(kk+1) * HID];
        acc += zc[kk+2] * wcol[(size_t)(kk+2) * HID];
        acc += zc[kk+3] * wcol[(size_t)(kk+3) * HID];
    }
    for (; kk < klen; ++kk)
        acc += zc[kk] * wcol[(size_t)kk * HID];

    atomicAdd(&g_zacc[b * HID + t], acc);
}

// ---------------- relu + fc2 ----------------
__global__ void __launch_bounds__(128) fin_kernel(
    const float* __restrict__ fcW2, const float* __restrict__ fcb2, float* __restrict__ out)
{
    __shared__ float sm[HID];
    int b = blockIdx.x, t = threadIdx.x;
    sm[t] = fmaxf(g_zacc[b * HID + t], 0.f);
    __syncthreads();
    if (t < NACT) {
        float o = fcb2[t];
#pragma unroll 8
        for (int h = 0; h < HID; ++h)
            o += sm[h] * fcW2[h * NACT + t];
        out[b * NACT + t] = o;
    }
}

// ---------------- launch ----------------
extern "C" void kernel_launch(void* const* d_in, const int* in_sizes, int n_in,
                              void* d_out, int out_size)
{
    const float* idxin = (const float*)d_in[0];   // [8,4096]
    const float* x     = (const float*)d_in[1];   // [8,4096,3]
    const float* y     = (const float*)d_in[2];   // [8,12,3]
    const int*   adj   = (const int*)  d_in[3];   // [8,4096,4096]
    const float* W1    = (const float*)d_in[4];
    const float* b1    = (const float*)d_in[5];
    const float* W2    = (const float*)d_in[6];
    const float* b2    = (const float*)d_in[7];
    const float* fcW1  = (const float*)d_in[8];
    const float* fcb1  = (const float*)d_in[9];
    const float* fcW2  = (const float*)d_in[10];
    const float* fcb2  = (const float*)d_in[11];
    float* out = (float*)d_out;

    prep_kernel<<<ROWS / 2, 256>>>(adj, x, W1, fcb1);
    agg_kernel<0><<<1024, 256>>>();
    v2_kernel<<<ROWS / 256, 256>>>(W2, b1);
    agg_kernel<1><<<1024, 256>>>();
    combine2_kernel<<<ROWS / 256, 256>>>(b2);
    fc1_kernel<<<BB * 32, 128>>>(idxin, y, fcW1);
    fin_kernel<<<BB, 128>>>(fcW2, fcb2, out);
}

// round 8
// speedup vs baseline: 1.4336x; 1.1468x over previous
#include <cuda_runtime.h>
#include <cuda_bf16.h>

typedef unsigned long long ull;

// Problem constants
#define BB    8
#define NN    4096
#define WROW  128          // 4096/32 bitmask words per row
#define ROWS  (BB*NN)      // 32768
#define INDIM 16420
#define HID   128
#define NACT  16
#define CK    514          // fc1 split-K chunk (32*514 >= 16420)
#define NQ    8            // column strips per row in agg (512 cols each)

// Bit layout (permuted, consistent between prep and agg):
//   word (rd*4 + e), bit l  <->  column rd*128 + l*4 + e     (rd 0..31, e 0..3, l 0..31)

// ---------------- scratch (static __device__, no allocations) ----------------
__device__ unsigned g_bits[(size_t)ROWS * WROW];   // 16 MB packed adjacency (with self loops)
__device__ float    g_dinv[ROWS];
__device__ float4   g_v [ROWS];                    // dinv * (x @ W1)
__device__ float4   g_v2[ROWS];                    // dinv * (h @ W2)
__device__ float4   g_h2[ROWS];                    // final GCN output h (layer2)
__device__ float4   g_pa[NQ * ROWS];               // layer1 partial sums (col strips)
__device__ float4   g_pb[NQ * ROWS];               // layer2 partial sums
__device__ float    g_zacc[BB * HID];

// ---------------- K1: adj -> bitmask (ballot, warp per row, no sync) ----------------
__global__ void __launch_bounds__(256) prep_kernel(const int* __restrict__ adj)
{
    int warp = (blockIdx.x * 256 + threadIdx.x) >> 5;   // 0..32767 = row
    int lane = threadIdx.x & 31;
    int row  = warp;
    int i    = row & (NN - 1);

    const int4* arow = (const int4*)(adj + ((size_t)row << 12));
    unsigned*   brow = g_bits + ((size_t)row << 7);

    // self-loop target: word tw, bit tb
    int tw = (i >> 7) * 4 + (i & 3);
    unsigned tb = 1u << ((i >> 2) & 31);

    int4 buf[4];
#pragma unroll
    for (int p = 0; p < 4; ++p)
        buf[p] = __ldcs(&arow[p * 32 + lane]);

#pragma unroll 1
    for (int g = 0; g < 8; ++g) {
        int4 cur[4];
#pragma unroll
        for (int p = 0; p < 4; ++p) cur[p] = buf[p];
        if (g < 7) {
#pragma unroll
            for (int p = 0; p < 4; ++p)
                buf[p] = __ldcs(&arow[(g + 1) * 128 + p * 32 + lane]);
        }
#pragma unroll
        for (int p = 0; p < 4; ++p) {
            int rd = g * 4 + p;
            int4 v = cur[p];
            unsigned b0 = __ballot_sync(0xffffffffu, v.x != 0);
            unsigned b1 = __ballot_sync(0xffffffffu, v.y != 0);
            unsigned b2 = __ballot_sync(0xffffffffu, v.z != 0);
            unsigned b3 = __ballot_sync(0xffffffffu, v.w != 0);
            if (lane < 4) {
                unsigned w = (lane == 0) ? b0 : (lane == 1) ? b1 : (lane == 2) ? b2 : b3;
                int widx = rd * 4 + lane;
                if (widx == tw) w |= tb;
                brow[widx] = w;
            }
        }
    }
}

// ---------------- K2: dinv + v1 + zacc init (warp per row) ----------------
__global__ void __launch_bounds__(256) dinv_v1_kernel(
    const float* __restrict__ x, const float* __restrict__ W1,
    const float* __restrict__ fcb1)
{
    int t    = threadIdx.x;
    int warp = (blockIdx.x * 256 + t) >> 5;   // row
    int lane = t & 31;

    if (blockIdx.x < 4 && t < HID) {
        g_zacc[(blockIdx.x * 2) * HID + t] = fcb1[t];
        g_zacc[(blockIdx.x * 2 + 1) * HID + t] = fcb1[t];
    }

    const uint4* bw = (const uint4*)(g_bits + ((size_t)warp << 7));
    uint4 w = bw[lane];
    unsigned cnt = __popc(w.x) + __popc(w.y) + __popc(w.z) + __popc(w.w);
    cnt = __reduce_add_sync(0xffffffffu, cnt);
    if (lane == 0) {
        float d = rsqrtf((float)cnt);
        g_dinv[warp] = d;
        float x0 = x[warp*3], x1 = x[warp*3+1], x2 = x[warp*3+2];
        float u0 = x0*W1[0] + x1*W1[3] + x2*W1[6];
        float u1 = x0*W1[1] + x1*W1[4] + x2*W1[7];
        float u2 = x0*W1[2] + x1*W1[5] + x2*W1[8];
        g_v[warp] = make_float4(d*u0, d*u1, d*u2, 0.f);
    }
}

// ---------------- quad-LUT aggregation (permuted bit order) ----------------
// Quad (word j, nibble k) in strip q covers columns:
//   base = q*512 + (j>>2)*128 + k*16 + (j&3),  cols = base + {0,4,8,12}

// grid = 1024 blocks: (b in 8) x (rowtile in 16: 256 rows) x (strip in 8: 512 cols)
template<int L>
__global__ void __launch_bounds__(256) agg_kernel()
{
    __shared__ float2 sxy[128 * 16];   // 16 KB
    __shared__ float  szl[128 * 16];   // 8 KB

    const float4* vin  = (L == 0) ? g_v  : g_v2;
    float4*       part = (L == 0) ? g_pa : g_pb;

    int bx = blockIdx.x;
    int b  = bx >> 7;
    int rt = (bx >> 3) & 15;
    int q  = bx & 7;
    int t  = threadIdx.x;

    // ---- build LUTs: thread t -> quad t>>1, entries (t&1)*8 .. +8 ----
    {
        int quad = t >> 1;              // 0..127 = j*8 + k
        int j = quad >> 3, k = quad & 7;
        int base = b * NN + q * 512 + (j >> 2) * 128 + k * 16 + (j & 3);
        float4 v0 = vin[base], v1 = vin[base + 4], v2 = vin[base + 8], v3 = vin[base + 12];
        int e0 = (t & 1) * 8;
        float2* exy = &sxy[quad * 16];
        float*  ez  = &szl[quad * 16];
#pragma unroll
        for (int e = 0; e < 8; ++e) {
            int i = e0 + e;
            float sx = 0.f, sy = 0.f, sz = 0.f;
            if (i & 1) { sx += v0.x; sy += v0.y; sz += v0.z; }
            if (i & 2) { sx += v1.x; sy += v1.y; sz += v1.z; }
            if (i & 4) { sx += v2.x; sy += v2.y; sz += v2.z; }
            if (i & 8) { sx += v3.x; sy += v3.y; sz += v3.z; }
            exy[i] = make_float2(sx, sy);
            ez[i]  = sz;
        }
    }
    __syncthreads();

    int row = b * NN + rt * 256 + t;

    const uint4* gw = (const uint4*)(g_bits + (size_t)row * WROW + q * 16);
    uint4 w0 = gw[0], w1 = gw[1], w2 = gw[2], w3 = gw[3];
    unsigned words[16] = { w0.x, w0.y, w0.z, w0.w, w1.x, w1.y, w1.z, w1.w,
                           w2.x, w2.y, w2.z, w2.w, w3.x, w3.y, w3.z, w3.w };

    unsigned bxy = (unsigned)__cvta_generic_to_shared(sxy);
    unsigned bz  = (unsigned)__cvta_generic_to_shared(szl);

    ull  accxy = 0ull;
    float accz = 0.f;

#pragma unroll
    for (int wl = 0; wl < 16; ++wl) {
        unsigned w = words[wl];
        unsigned rxy = bxy + wl * 1024;   // 8 quads * 128B
        unsigned rz  = bz  + wl * 512;    // 8 quads * 64B
#pragma unroll
        for (int k = 0; k < 8; ++k) {
            unsigned idx = (w >> (4 * k)) & 15u;
            unsigned axy = rxy + k * 128 + idx * 8;
            unsigned az  = rz  + k * 64  + idx * 4;
            ull vxy;
            asm volatile("ld.shared.b64 %0, [%1];" : "=l"(vxy) : "r"(axy));
            asm volatile("add.rn.f32x2 %0, %0, %1;" : "+l"(accxy) : "l"(vxy));
            float vz;
            asm volatile("ld.shared.f32 %0, [%1];" : "=f"(vz) : "r"(az));
            accz += vz;
        }
    }

    float ax, ay;
    asm volatile("mov.b64 {%0, %1}, %2;" : "=f"(ax), "=f"(ay) : "l"(accxy));
    part[q * ROWS + row] = make_float4(ax, ay, accz, 0.f);
}

// ---------------- combine layer1 partials, relu, v2 = dinv * (h @ W2) ----------------
__global__ void v2_kernel(const float* __restrict__ W2, const float* __restrict__ b1)
{
    int id = blockIdx.x * blockDim.x + threadIdx.x;
    if (id >= ROWS) return;
    float sx = 0.f, sy = 0.f, sz = 0.f;
#pragma unroll
    for (int qq = 0; qq < NQ; ++qq) {
        float4 p = g_pa[qq * ROWS + id];
        sx += p.x; sy += p.y; sz += p.z;
    }
    float d = g_dinv[id];
    float h0 = fmaxf(d * sx + b1[0], 0.f);
    float h1 = fmaxf(d * sy + b1[1], 0.f);
    float h2 = fmaxf(d * sz + b1[2], 0.f);
    float u0 = h0*W2[0] + h1*W2[3] + h2*W2[6];
    float u1 = h0*W2[1] + h1*W2[4] + h2*W2[7];
    float u2 = h0*W2[2] + h1*W2[5] + h2*W2[8];
    g_v2[id] = make_float4(d*u0, d*u1, d*u2, 0.f);
}

// ---------------- combine layer2 partials -> final GCN h ----------------
__global__ void combine2_kernel(const float* __restrict__ b2)
{
    int id = blockIdx.x * blockDim.x + threadIdx.x;
    if (id >= ROWS) return;
    float sx = 0.f, sy = 0.f, sz = 0.f;
#pragma unroll
    for (int qq = 0; qq < NQ; ++qq) {
        float4 p = g_pb[qq * ROWS + id];
        sx += p.x; sy += p.y; sz += p.z;
    }
    float d = g_dinv[id];
    g_h2[id] = make_float4(d * sx + b2[0], d * sy + b2[1], d * sz + b2[2], 0.f);
}

// ---------------- fc1 split-K, z built on the fly, atomic accumulate ----------------
__global__ void __launch_bounds__(128) fc1_kernel(
    const float* __restrict__ idxin, const float* __restrict__ y,
    const float* __restrict__ fcW1)
{
    __shared__ float zc[CK];
    int bx = blockIdx.x;
    int b  = bx >> 5;
    int s  = bx & 31;
    int k0 = s * CK;
    int klen = min(CK, INDIM - k0);
    int t = threadIdx.x;

    for (int kk = t; kk < klen; kk += 128) {
        int k = k0 + kk;
        float z;
        if (k < NN) {
            z = idxin[b * NN + k];
        } else if (k < NN + 3 * NN) {
            int g = k - NN;
            int i = g / 3;
            int f = g - i * 3;
            z = ((const float*)&g_h2[b * NN + i])[f];
        } else {
            z = y[b * 36 + (k - (NN + 3 * NN))];
        }
        zc[kk] = z;
    }
    __syncthreads();

    float acc = 0.f;
    const float* wcol = fcW1 + (size_t)k0 * HID + t;
    int kk = 0;
    for (; kk + 4 <= klen; kk += 4) {
        acc += zc[kk+0] * wcol[(size_t)(kk+0) * HID];
        acc += zc[kk+1] * wcol[(size_t)(kk+1) * HID];
        acc += zc[kk+2] * wcol[(size_t)(kk+2) * HID];
        acc += zc[kk+3] * wcol[(size_t)(kk+3) * HID];
    }
    for (; kk < klen; ++kk)
        acc += zc[kk] * wcol[(size_t)kk * HID];

    atomicAdd(&g_zacc[b * HID + t], acc);
}

// ---------------- relu + fc2 ----------------
__global__ void __launch_bounds__(128) fin_kernel(
    const float* __restrict__ fcW2, const float* __restrict__ fcb2, float* __restrict__ out)
{
    __shared__ float sm[HID];
    int b = blockIdx.x, t = threadIdx.x;
    sm[t] = fmaxf(g_zacc[b * HID + t], 0.f);
    __syncthreads();
    if (t < NACT) {
        float o = fcb2[t];
#pragma unroll 8
        for (int h = 0; h < HID; ++h)
            o += sm[h] * fcW2[h * NACT + t];
        out[b * NACT + t] = o;
    }
}

// ---------------- launch ----------------
extern "C" void kernel_launch(void* const* d_in, const int* in_sizes, int n_in,
                              void* d_out, int out_size)
{
    const float* idxin = (const float*)d_in[0];   // [8,4096]
    const float* x     = (const float*)d_in[1];   // [8,4096,3]
    const float* y     = (const float*)d_in[2];   // [8,12,3]
    const int*   adj   = (const int*)  d_in[3];   // [8,4096,4096]
    const float* W1    = (const float*)d_in[4];
    const float* b1    = (const float*)d_in[5];
    const float* W2    = (const float*)d_in[6];
    const float* b2    = (const float*)d_in[7];
    const float* fcW1  = (const float*)d_in[8];
    const float* fcb1  = (const float*)d_in[9];
    const float* fcW2  = (const float*)d_in[10];
    const float* fcb2  = (const float*)d_in[11];
    float* out = (float*)d_out;

    prep_kernel<<<ROWS / 8, 256>>>(adj);              // 8 warps/block, warp per row
    dinv_v1_kernel<<<ROWS / 8, 256>>>(x, W1, fcb1);
    agg_kernel<0><<<1024, 256>>>();
    v2_kernel<<<ROWS / 256, 256>>>(W2, b1);
    agg_kernel<1><<<1024, 256>>>();
    combine2_kernel<<<ROWS / 256, 256>>>(b2);
    fc1_kernel<<<BB * 32, 128>>>(idxin, y, fcW1);
    fin_kernel<<<BB, 128>>>(fcW2, fcb2, out);
}

// round 9
// speedup vs baseline: 1.5063x; 1.0507x over previous
#include <cuda_runtime.h>
#include <cuda_bf16.h>

typedef unsigned long long ull;

// Problem constants
#define BB    8
#define NN    4096
#define WROW  128          // 4096/32 bitmask words per row
#define ROWS  (BB*NN)      // 32768
#define INDIM 16420
#define HID   128
#define NACT  16
#define CK    514          // fc1 split-K chunk (32*514 >= 16420)
#define NQ    16           // column strips per row in agg (256 cols each)

// Bit layout (permuted, consistent between prep and agg):
//   word (rd*4 + e), bit l  <->  column rd*128 + l*4 + e     (rd 0..31, e 0..3, l 0..31)

// ---------------- scratch (static __device__, no allocations) ----------------
__device__ unsigned g_bits[(size_t)ROWS * WROW];   // 16 MB packed adjacency (with self loops)
__device__ float    g_dinv[ROWS];
__device__ float4   g_v [ROWS];                    // dinv * (x @ W1)
__device__ float4   g_v2[ROWS];                    // dinv * (h @ W2)
__device__ float4   g_h2[ROWS];                    // final GCN output h (layer2)
__device__ float4   g_pa[NQ * ROWS];               // layer1 partial sums (col strips)
__device__ float4   g_pb[NQ * ROWS];               // layer2 partial sums
__device__ float    g_zacc[BB * HID];

// ---------------- K1: adj -> bitmask + dinv + v1 + zacc (ballot, warp/row) ------
__global__ void __launch_bounds__(256) prep_kernel(
    const int* __restrict__ adj, const float* __restrict__ x,
    const float* __restrict__ W1, const float* __restrict__ fcb1)
{
    int t    = threadIdx.x;
    int warp = (blockIdx.x * 256 + t) >> 5;   // 0..32767 = row
    int lane = t & 31;
    int row  = warp;
    int i    = row & (NN - 1);

    // fused zacc init (block 0 covers all 1024 entries)
    if (blockIdx.x == 0) {
#pragma unroll
        for (int r = 0; r < 4; ++r) {
            int idx = r * 256 + t;
            g_zacc[idx] = fcb1[idx & (HID - 1)];
        }
    }

    const int4* arow = (const int4*)(adj + ((size_t)row << 12));
    unsigned*   brow = g_bits + ((size_t)row << 7);

    // self-loop target: word tw, bit tb
    int tw = (i >> 7) * 4 + (i & 3);
    unsigned tb = 1u << ((i >> 2) & 31);

    int4 buf[4];
#pragma unroll
    for (int p = 0; p < 4; ++p)
        buf[p] = __ldcs(&arow[p * 32 + lane]);

    unsigned cnt = 0;

#pragma unroll 1
    for (int g = 0; g < 8; ++g) {
        int4 cur[4];
#pragma unroll
        for (int p = 0; p < 4; ++p) cur[p] = buf[p];
        if (g < 7) {
#pragma unroll
            for (int p = 0; p < 4; ++p)
                buf[p] = __ldcs(&arow[(g + 1) * 128 + p * 32 + lane]);
        }
#pragma unroll
        for (int p = 0; p < 4; ++p) {
            int rd = g * 4 + p;
            int4 v = cur[p];
            unsigned b0 = __ballot_sync(0xffffffffu, v.x != 0);
            unsigned b1 = __ballot_sync(0xffffffffu, v.y != 0);
            unsigned b2 = __ballot_sync(0xffffffffu, v.z != 0);
            unsigned b3 = __ballot_sync(0xffffffffu, v.w != 0);
            if (lane < 4) {
                unsigned w = (lane == 0) ? b0 : (lane == 1) ? b1 : (lane == 2) ? b2 : b3;
                int widx = rd * 4 + lane;
                if (widx == tw) w |= tb;
                brow[widx] = w;
                cnt += __popc(w);
            }
        }
    }

    // fused degree + dinv + v1
    cnt = __reduce_add_sync(0xffffffffu, cnt);
    if (lane == 0) {
        float d = rsqrtf((float)cnt);
        g_dinv[row] = d;
        float x0 = x[row*3], x1 = x[row*3+1], x2 = x[row*3+2];
        float u0 = x0*W1[0] + x1*W1[3] + x2*W1[6];
        float u1 = x0*W1[1] + x1*W1[4] + x2*W1[7];
        float u2 = x0*W1[2] + x1*W1[5] + x2*W1[8];
        g_v[row] = make_float4(d*u0, d*u1, d*u2, 0.f);
    }
}

// ---------------- quad-LUT aggregation (permuted bit order) ----------------
// Strip s covers columns [s*256, s*256+256) = words [s*8, s*8+8).
// Quad (word j in 0..7, nibble k in 0..7) covers columns:
//   base = s*256 + (j>>2)*128 + k*16 + (j&3),  cols = base + {0,4,8,12}
// (valid because s*8 is a multiple of 4, so rd = 2s + (j>>2), e = j&3)

// grid = 2048 blocks: (b in 8) x (rowtile in 16: 256 rows) x (strip in 16)
template<int L>
__global__ void __launch_bounds__(256) agg_kernel()
{
    __shared__ float2 sxy[64 * 16];   // 8 KB
    __shared__ float  szl[64 * 16];   // 4 KB

    const float4* vin  = (L == 0) ? g_v  : g_v2;
    float4*       part = (L == 0) ? g_pa : g_pb;

    int bx = blockIdx.x;
    int b  = bx >> 8;
    int rt = (bx >> 4) & 15;
    int s  = bx & 15;
    int t  = threadIdx.x;

    // ---- build LUTs: thread t -> quad t>>2, entries (t&3)*4 .. +4 ----
    {
        int quad = t >> 2;              // 0..63 = j*8 + k
        int j = quad >> 3, k = quad & 7;
        int base = b * NN + s * 256 + (j >> 2) * 128 + k * 16 + (j & 3);
        float4 v0 = vin[base], v1 = vin[base + 4], v2 = vin[base + 8], v3 = vin[base + 12];
        int e0 = (t & 3) * 4;
        float2* exy = &sxy[quad * 16];
        float*  ez  = &szl[quad * 16];
#pragma unroll
        for (int e = 0; e < 4; ++e) {
            int i = e0 + e;
            float sx = 0.f, sy = 0.f, sz = 0.f;
            if (i & 1) { sx += v0.x; sy += v0.y; sz += v0.z; }
            if (i & 2) { sx += v1.x; sy += v1.y; sz += v1.z; }
            if (i & 4) { sx += v2.x; sy += v2.y; sz += v2.z; }
            if (i & 8) { sx += v3.x; sy += v3.y; sz += v3.z; }
            exy[i] = make_float2(sx, sy);
            ez[i]  = sz;
        }
    }
    __syncthreads();

    int row = b * NN + rt * 256 + t;

    const uint4* gw = (const uint4*)(g_bits + (size_t)row * WROW + s * 8);
    uint4 w0 = gw[0], w1 = gw[1];
    unsigned words[8] = { w0.x, w0.y, w0.z, w0.w, w1.x, w1.y, w1.z, w1.w };

    unsigned bxy = (unsigned)__cvta_generic_to_shared(sxy);
    unsigned bz  = (unsigned)__cvta_generic_to_shared(szl);

    ull  accxy = 0ull;
    float accz = 0.f;

#pragma unroll
    for (int wl = 0; wl < 8; ++wl) {
        unsigned w = words[wl];
        unsigned rxy = bxy + wl * 1024;   // 8 quads * 128B
        unsigned rz  = bz  + wl * 512;    // 8 quads * 64B
#pragma unroll
        for (int k = 0; k < 8; ++k) {
            unsigned idx = (w >> (4 * k)) & 15u;
            unsigned axy = rxy + k * 128 + idx * 8;
            unsigned az  = rz  + k * 64  + idx * 4;
            ull vxy;
            asm volatile("ld.shared.b64 %0, [%1];" : "=l"(vxy) : "r"(axy));
            asm volatile("add.rn.f32x2 %0, %0, %1;" : "+l"(accxy) : "l"(vxy));
            float vz;
            asm volatile("ld.shared.f32 %0, [%1];" : "=f"(vz) : "r"(az));
            accz += vz;
        }
    }

    float ax, ay;
    asm volatile("mov.b64 {%0, %1}, %2;" : "=f"(ax), "=f"(ay) : "l"(accxy));
    part[s * ROWS + row] = make_float4(ax, ay, accz, 0.f);
}

// ---------------- combine layer1 partials, relu, v2 = dinv * (h @ W2) ----------------
__global__ void __launch_bounds__(64) v2_kernel(const float* __restrict__ W2, const float* __restrict__ b1)
{
    int id = blockIdx.x * 64 + threadIdx.x;
    if (id >= ROWS) return;
    float sx = 0.f, sy = 0.f, sz = 0.f;
#pragma unroll
    for (int qq = 0; qq < NQ; ++qq) {
        float4 p = g_pa[qq * ROWS + id];
        sx += p.x; sy += p.y; sz += p.z;
    }
    float d = g_dinv[id];
    float h0 = fmaxf(d * sx + b1[0], 0.f);
    float h1 = fmaxf(d * sy + b1[1], 0.f);
    float h2 = fmaxf(d * sz + b1[2], 0.f);
    float u0 = h0*W2[0] + h1*W2[3] + h2*W2[6];
    float u1 = h0*W2[1] + h1*W2[4] + h2*W2[7];
    float u2 = h0*W2[2] + h1*W2[5] + h2*W2[8];
    g_v2[id] = make_float4(d*u0, d*u1, d*u2, 0.f);
}

// ---------------- combine layer2 partials -> final GCN h ----------------
__global__ void __launch_bounds__(64) combine2_kernel(const float* __restrict__ b2)
{
    int id = blockIdx.x * 64 + threadIdx.x;
    if (id >= ROWS) return;
    float sx = 0.f, sy = 0.f, sz = 0.f;
#pragma unroll
    for (int qq = 0; qq < NQ; ++qq) {
        float4 p = g_pb[qq * ROWS + id];
        sx += p.x; sy += p.y; sz += p.z;
    }
    float d = g_dinv[id];
    g_h2[id] = make_float4(d * sx + b2[0], d * sy + b2[1], d * sz + b2[2], 0.f);
}

// ---------------- fc1 split-K, z built on the fly, atomic accumulate ----------------
__global__ void __launch_bounds__(128) fc1_kernel(
    const float* __restrict__ idxin, const float* __restrict__ y,
    const float* __restrict__ fcW1)
{
    __shared__ float zc[CK];
    int bx = blockIdx.x;
    int b  = bx >> 5;
    int s  = bx & 31;
    int k0 = s * CK;
    int klen = min(CK, INDIM - k0);
    int t = threadIdx.x;

    for (int kk = t; kk < klen; kk += 128) {
        int k = k0 + kk;
        float z;
        if (k < NN) {
            z = idxin[b * NN + k];
        } else if (k < NN + 3 * NN) {
            int g = k - NN;
            int i = g / 3;
            int f = g - i * 3;
            z = ((const float*)&g_h2[b * NN + i])[f];
        } else {
            z = y[b * 36 + (k - (NN + 3 * NN))];
        }
        zc[kk] = z;
    }
    __syncthreads();

    float acc = 0.f;
    const float* wcol = fcW1 + (size_t)k0 * HID + t;
    int kk = 0;
    for (; kk + 4 <= klen; kk += 4) {
        acc += zc[kk+0] * wcol[(size_t)(kk+0) * HID];
        acc += zc[kk+1] * wcol[(size_t)(kk+1) * HID];
        acc += zc[kk+2] * wcol[(size_t)(kk+2) * HID];
        acc += zc[kk+3] * wcol[(size_t)(kk+3) * HID];
    }
    for (; kk < klen; ++kk)
        acc += zc[kk] * wcol[(size_t)kk * HID];

    atomicAdd(&g_zacc[b * HID + t], acc);
}

// ---------------- relu + fc2 ----------------
__global__ void __launch_bounds__(128) fin_kernel(
    const float* __restrict__ fcW2, const float* __restrict__ fcb2, float* __restrict__ out)
{
    __shared__ float sm[HID];
    int b = blockIdx.x, t = threadIdx.x;
    sm[t] = fmaxf(g_zacc[b * HID + t], 0.f);
    __syncthreads();
    if (t < NACT) {
        float o = fcb2[t];
#pragma unroll 8
        for (int h = 0; h < HID; ++h)
            o += sm[h] * fcW2[h * NACT + t];
        out[b * NACT + t] = o;
    }
}

// ---------------- launch ----------------
extern "C" void kernel_launch(void* const* d_in, const int* in_sizes, int n_in,
                              void* d_out, int out_size)
{
    const float* idxin = (const float*)d_in[0];   // [8,4096]
    const float* x     = (const float*)d_in[1];   // [8,4096,3]
    const float* y     = (const float*)d_in[2];   // [8,12,3]
    const int*   adj   = (const int*)  d_in[3];   // [8,4096,4096]
    const float* W1    = (const float*)d_in[4];
    const float* b1    = (const float*)d_in[5];
    const float* W2    = (const float*)d_in[6];
    const float* b2    = (const float*)d_in[7];
    const float* fcW1  = (const float*)d_in[8];
    const float* fcb1  = (const float*)d_in[9];
    const float* fcW2  = (const float*)d_in[10];
    const float* fcb2  = (const float*)d_in[11];
    float* out = (float*)d_out;

    prep_kernel<<<ROWS / 8, 256>>>(adj, x, W1, fcb1);
    agg_kernel<0><<<2048, 256>>>();
    v2_kernel<<<ROWS / 64, 64>>>(W2, b1);
    agg_kernel<1><<<2048, 256>>>();
    combine2_kernel<<<ROWS / 64, 64>>>(b2);
    fc1_kernel<<<BB * 32, 128>>>(idxin, y, fcW1);
    fin_kernel<<<BB, 128>>>(fcW2, fcb2, out);
}

// round 10
// speedup vs baseline: 1.5085x; 1.0014x over previous
#include <cuda_runtime.h>
#include <cuda_bf16.h>

typedef unsigned long long ull;

// Problem constants
#define BB    8
#define NN    4096
#define WROW  128          // 4096/32 bitmask words per row
#define ROWS  (BB*NN)      // 32768
#define INDIM 16420
#define HID   128
#define NACT  16
#define CK    514          // fc1 split-K chunk (32*514 >= 16420)
#define NQ    16           // column strips per row in agg (256 cols each)

// Bit layout (permuted, consistent between prep and agg):
//   word (rd*4 + e), bit l  <->  column rd*128 + l*4 + e     (rd 0..31, e 0..3, l 0..31)

// ---------------- scratch (static __device__, no allocations) ----------------
__device__ unsigned g_bits[(size_t)ROWS * WROW];   // 16 MB packed adjacency (with self loops)
__device__ float    g_dinv[ROWS];
__device__ float4   g_v [ROWS];                    // dinv * (x @ W1)
__device__ float4   g_v2[ROWS];                    // dinv * (h @ W2)
__device__ float4   g_h2[ROWS];                    // final GCN output h (layer2)
__device__ float4   g_pa[NQ * ROWS];               // layer1 partial sums (col strips)
__device__ float4   g_pb[NQ * ROWS];               // layer2 partial sums
__device__ float    g_zacc[BB * HID];

// ---------------- K1: adj -> bitmask + dinv + v1 + zacc (ballot, warp/row) ------
// 8-deep LDG.128 pipeline: 8 loads in flight per warp, 4 ballot rounds.
__global__ void __launch_bounds__(256) prep_kernel(
    const int* __restrict__ adj, const float* __restrict__ x,
    const float* __restrict__ W1, const float* __restrict__ fcb1)
{
    int t    = threadIdx.x;
    int warp = (blockIdx.x * 256 + t) >> 5;   // 0..32767 = row
    int lane = t & 31;
    int row  = warp;
    int i    = row & (NN - 1);

    // fused zacc init (block 0 covers all 1024 entries)
    if (blockIdx.x == 0) {
#pragma unroll
        for (int r = 0; r < 4; ++r) {
            int idx = r * 256 + t;
            g_zacc[idx] = fcb1[idx & (HID - 1)];
        }
    }

    const int4* arow = (const int4*)(adj + ((size_t)row << 12));
    unsigned*   brow = g_bits + ((size_t)row << 7);

    // self-loop target: word tw, bit tb
    int tw = (i >> 7) * 4 + (i & 3);
    unsigned tb = 1u << ((i >> 2) & 31);

    int4 buf[8];
#pragma unroll
    for (int p = 0; p < 8; ++p)
        buf[p] = __ldcs(&arow[p * 32 + lane]);

    unsigned cnt = 0;

#pragma unroll 1
    for (int g = 0; g < 4; ++g) {
        int4 cur[8];
#pragma unroll
        for (int p = 0; p < 8; ++p) cur[p] = buf[p];
        if (g < 3) {
#pragma unroll
            for (int p = 0; p < 8; ++p)
                buf[p] = __ldcs(&arow[(g + 1) * 256 + p * 32 + lane]);
        }
#pragma unroll
        for (int p = 0; p < 8; ++p) {
            int rd = g * 8 + p;
            int4 v = cur[p];
            unsigned b0 = __ballot_sync(0xffffffffu, v.x != 0);
            unsigned b1 = __ballot_sync(0xffffffffu, v.y != 0);
            unsigned b2 = __ballot_sync(0xffffffffu, v.z != 0);
            unsigned b3 = __ballot_sync(0xffffffffu, v.w != 0);
            if (lane < 4) {
                unsigned w = (lane == 0) ? b0 : (lane == 1) ? b1 : (lane == 2) ? b2 : b3;
                int widx = rd * 4 + lane;
                if (widx == tw) w |= tb;
                brow[widx] = w;
                cnt += __popc(w);
            }
        }
    }

    // fused degree + dinv + v1
    cnt = __reduce_add_sync(0xffffffffu, cnt);
    if (lane == 0) {
        float d = rsqrtf((float)cnt);
        g_dinv[row] = d;
        float x0 = x[row*3], x1 = x[row*3+1], x2 = x[row*3+2];
        float u0 = x0*W1[0] + x1*W1[3] + x2*W1[6];
        float u1 = x0*W1[1] + x1*W1[4] + x2*W1[7];
        float u2 = x0*W1[2] + x1*W1[5] + x2*W1[8];
        g_v[row] = make_float4(d*u0, d*u1, d*u2, 0.f);
    }
}

// ---------------- quad-LUT aggregation (permuted bit order) ----------------
// Strip s covers columns [s*256, s*256+256) = words [s*8, s*8+8).
// Quad (word j in 0..7, nibble k in 0..7) covers columns:
//   base = s*256 + (j>>2)*128 + k*16 + (j&3),  cols = base + {0,4,8,12}

// grid = 2048 blocks: (b in 8) x (rowtile in 16: 256 rows) x (strip in 16)
template<int L>
__global__ void __launch_bounds__(256) agg_kernel()
{
    __shared__ float2 sxy[64 * 16];   // 8 KB
    __shared__ float  szl[64 * 16];   // 4 KB

    const float4* vin  = (L == 0) ? g_v  : g_v2;
    float4*       part = (L == 0) ? g_pa : g_pb;

    int bx = blockIdx.x;
    int b  = bx >> 8;
    int rt = (bx >> 4) & 15;
    int s  = bx & 15;
    int t  = threadIdx.x;

    // ---- build LUTs: thread t -> quad t>>2, entries (t&3)*4 .. +4 ----
    {
        int quad = t >> 2;              // 0..63 = j*8 + k
        int j = quad >> 3, k = quad & 7;
        int base = b * NN + s * 256 + (j >> 2) * 128 + k * 16 + (j & 3);
        float4 v0 = vin[base], v1 = vin[base + 4], v2 = vin[base + 8], v3 = vin[base + 12];
        int e0 = (t & 3) * 4;
        float2* exy = &sxy[quad * 16];
        float*  ez  = &szl[quad * 16];
#pragma unroll
        for (int e = 0; e < 4; ++e) {
            int i = e0 + e;
            float sx = 0.f, sy = 0.f, sz = 0.f;
            if (i & 1) { sx += v0.x; sy += v0.y; sz += v0.z; }
            if (i & 2) { sx += v1.x; sy += v1.y; sz += v1.z; }
            if (i & 4) { sx += v2.x; sy += v2.y; sz += v2.z; }
            if (i & 8) { sx += v3.x; sy += v3.y; sz += v3.z; }
            exy[i] = make_float2(sx, sy);
            ez[i]  = sz;
        }
    }
    __syncthreads();

    int row = b * NN + rt * 256 + t;

    const uint4* gw = (const uint4*)(g_bits + (size_t)row * WROW + s * 8);
    uint4 w0 = gw[0], w1 = gw[1];
    unsigned words[8] = { w0.x, w0.y, w0.z, w0.w, w1.x, w1.y, w1.z, w1.w };

    unsigned bxy = (unsigned)__cvta_generic_to_shared(sxy);
    unsigned bz  = (unsigned)__cvta_generic_to_shared(szl);

    // dual accumulators break the RAW chain on the FMA pipe
    ull  accxy0 = 0ull, accxy1 = 0ull;
    float accz0 = 0.f,  accz1 = 0.f;

#pragma unroll
    for (int wl = 0; wl < 8; ++wl) {
        unsigned w = words[wl];
        unsigned rxy = bxy + wl * 1024;   // 8 quads * 128B
        unsigned rz  = bz  + wl * 512;    // 8 quads * 64B
#pragma unroll
        for (int k = 0; k < 8; k += 2) {
            unsigned idx0 = (w >> (4 * k)) & 15u;
            unsigned idx1 = (w >> (4 * k + 4)) & 15u;
            unsigned axy0 = rxy + k * 128 + idx0 * 8;
            unsigned axy1 = rxy + k * 128 + 128 + idx1 * 8;
            unsigned az0  = rz  + k * 64 + idx0 * 4;
            unsigned az1  = rz  + k * 64 + 64 + idx1 * 4;
            ull vxy0, vxy1;
            float vz0, vz1;
            asm volatile("ld.shared.b64 %0, [%1];" : "=l"(vxy0) : "r"(axy0));
            asm volatile("ld.shared.b64 %0, [%1];" : "=l"(vxy1) : "r"(axy1));
            asm volatile("ld.shared.f32 %0, [%1];" : "=f"(vz0) : "r"(az0));
            asm volatile("ld.shared.f32 %0, [%1];" : "=f"(vz1) : "r"(az1));
            asm volatile("add.rn.f32x2 %0, %0, %1;" : "+l"(accxy0) : "l"(vxy0));
            asm volatile("add.rn.f32x2 %0, %0, %1;" : "+l"(accxy1) : "l"(vxy1));
            accz0 += vz0;
            accz1 += vz1;
        }
    }

    ull accxy;
    asm volatile("add.rn.f32x2 %0, %1, %2;" : "=l"(accxy) : "l"(accxy0), "l"(accxy1));
    float ax, ay;
    asm volatile("mov.b64 {%0, %1}, %2;" : "=f"(ax), "=f"(ay) : "l"(accxy));
    part[s * ROWS + row] = make_float4(ax, ay, accz0 + accz1, 0.f);
}

// ---------------- combine layer1 partials, relu, v2 = dinv * (h @ W2) ----------------
__global__ void __launch_bounds__(64) v2_kernel(const float* __restrict__ W2, const float* __restrict__ b1)
{
    int id = blockIdx.x * 64 + threadIdx.x;
    if (id >= ROWS) return;
    float sx = 0.f, sy = 0.f, sz = 0.f;
#pragma unroll
    for (int qq = 0; qq < NQ; ++qq) {
        float4 p = g_pa[qq * ROWS + id];
        sx += p.x; sy += p.y; sz += p.z;
    }
    float d = g_dinv[id];
    float h0 = fmaxf(d * sx + b1[0], 0.f);
    float h1 = fmaxf(d * sy + b1[1], 0.f);
    float h2 = fmaxf(d * sz + b1[2], 0.f);
    float u0 = h0*W2[0] + h1*W2[3] + h2*W2[6];
    float u1 = h0*W2[1] + h1*W2[4] + h2*W2[7];
    float u2 = h0*W2[2] + h1*W2[5] + h2*W2[8];
    g_v2[id] = make_float4(d*u0, d*u1, d*u2, 0.f);
}

// ---------------- combine layer2 partials -> final GCN h ----------------
__global__ void __launch_bounds__(64) combine2_kernel(const float* __restrict__ b2)
{
    int id = blockIdx.x * 64 + threadIdx.x;
    if (id >= ROWS) return;
    float sx = 0.f, sy = 0.f, sz = 0.f;
#pragma unroll
    for (int qq = 0; qq < NQ; ++qq) {
        float4 p = g_pb[qq * ROWS + id];
        sx += p.x; sy += p.y; sz += p.z;
    }
    float d = g_dinv[id];
    g_h2[id] = make_float4(d * sx + b2[0], d * sy + b2[1], d * sz + b2[2], 0.f);
}

// ---------------- fc1 split-K, z built on the fly, atomic accumulate ----------------
__global__ void __launch_bounds__(128) fc1_kernel(
    const float* __restrict__ idxin, const float* __restrict__ y,
    const float* __restrict__ fcW1)
{
    __shared__ float zc[CK];
    int bx = blockIdx.x;
    int b  = bx >> 5;
    int s  = bx & 31;
    int k0 = s * CK;
    int klen = min(CK, INDIM - k0);
    int t = threadIdx.x;

    for (int kk = t; kk < klen; kk += 128) {
        int k = k0 + kk;
        float z;
        if (k < NN) {
            z = idxin[b * NN + k];
        } else if (k < NN + 3 * NN) {
            int g = k - NN;
            int i = g / 3;
            int f = g - i * 3;
            z = ((const float*)&g_h2[b * NN + i])[f];
        } else {
            z = y[b * 36 + (k - (NN + 3 * NN))];
        }
        zc[kk] = z;
    }
    __syncthreads();

    float acc = 0.f;
    const float* wcol = fcW1 + (size_t)k0 * HID + t;
    int kk = 0;
    for (; kk + 4 <= klen; kk += 4) {
        acc += zc[kk+0] * wcol[(size_t)(kk+0) * HID];
        acc += zc[kk+1] * wcol[(size_t)(kk+1) * HID];
        acc += zc[kk+2] * wcol[(size_t)(kk+2) * HID];
        acc += zc[kk+3] * wcol[(size_t)(kk+3) * HID];
    }
    for (; kk < klen; ++kk)
        acc += zc[kk] * wcol[(size_t)kk * HID];

    atomicAdd(&g_zacc[b * HID + t], acc);
}

// ---------------- relu + fc2 ----------------
__global__ void __launch_bounds__(128) fin_kernel(
    const float* __restrict__ fcW2, const float* __restrict__ fcb2, float* __restrict__ out)
{
    __shared__ float sm[HID];
    int b = blockIdx.x, t = threadIdx.x;
    sm[t] = fmaxf(g_zacc[b * HID + t], 0.f);
    __syncthreads();
    if (t < NACT) {
        float o = fcb2[t];
#pragma unroll 8
        for (int h = 0; h < HID; ++h)
            o += sm[h] * fcW2[h * NACT + t];
        out[b * NACT + t] = o;
    }
}

// ---------------- launch ----------------
extern "C" void kernel_launch(void* const* d_in, const int* in_sizes, int n_in,
                              void* d_out, int out_size)
{
    const float* idxin = (const float*)d_in[0];   // [8,4096]
    const float* x     = (const float*)d_in[1];   // [8,4096,3]
    const float* y     = (const float*)d_in[2];   // [8,12,3]
    const int*   adj   = (const int*)  d_in[3];   // [8,4096,4096]
    const float* W1    = (const float*)d_in[4];
    const float* b1    = (const float*)d_in[5];
    const float* W2    = (const float*)d_in[6];
    const float* b2    = (const float*)d_in[7];
    const float* fcW1  = (const float*)d_in[8];
    const float* fcb1  = (const float*)d_in[9];
    const float* fcW2  = (const float*)d_in[10];
    const float* fcb2  = (const float*)d_in[11];
    float* out = (float*)d_out;

    prep_kernel<<<ROWS / 8, 256>>>(adj, x, W1, fcb1);
    agg_kernel<0><<<2048, 256>>>();
    v2_kernel<<<ROWS / 64, 64>>>(W2, b1);
    agg_kernel<1><<<2048, 256>>>();
    combine2_kernel<<<ROWS / 64, 64>>>(b2);
    fc1_kernel<<<BB * 32, 128>>>(idxin, y, fcW1);
    fin_kernel<<<BB, 128>>>(fcW2, fcb2, out);
}